// round 16
// baseline (speedup 1.0000x reference)
#include <cuda_runtime.h>
#include <cuda_bf16.h>
#include <cstdint>

// Problem shape (fixed for this registry entry)
#define B     8
#define T     200
#define U1    101        // U+1
#define V     1024
#define UD    104        // padded cells per row
#define ND    300        // single-step diagonals (T + U1 - 1)
#define NQR   80         // padded quad-rows per batch (20 blocks of 4)
#define LN2   0.6931471805599453f
#define LOG2E 1.4426950408889634f

// Quad-step coefficient planes (SoA, conflict-free LDS):
//   A-plane: uint32 = bf16x2 (c0, c1)
//   B-plane: uint32 = bf16x2 (c2, c3)
//   C-plane: bf16   = c4
// a_{d+4}(u) = c0*a(u) + c1*a(u-1) + c2*a(u-2) + c3*a(u-3) + c4*a(u-4)
__device__ __align__(16) uint32_t      g_qA[B * NQR * UD];
__device__ __align__(16) uint32_t      g_qB[B * NQR * UD];
__device__ __align__(16) __nv_bfloat16 g_qC[B * NQR * UD];

__device__ __forceinline__ uint32_t smem_u32(const void* p) {
    uint32_t a;
    asm("{ .reg .u64 t; cvta.to.shared.u64 t, %1; cvt.u32.u64 %0, t; }"
        : "=r"(a) : "l"(p));
    return a;
}

// FMA-pipe exp (no MUFU/CVT), rel err ~5e-5 << bf16 storage precision
__device__ __forceinline__ float fexp(float x) {
    const float MAGIC = 12582912.0f;               // 1.5 * 2^23
    float z = fmaf(x, LOG2E, MAGIC);
    int   k = __float_as_int(z) - 0x4B400000;
    float r = z - MAGIC;
    float f = fmaf(x, LOG2E, -r);
    float p = fmaf(f, 0.0096181291f, 0.0555041087f);
    p = fmaf(f, p, 0.2402265069f);
    p = fmaf(f, p, 0.6931471806f);
    p = fmaf(f, p, 1.0f);
    return __int_as_float(__float_as_int(p) + (k << 23));
}

// Single-step scores (neutral-padded, proven R5..R13):
//   Bl(r,u)=exp(blank[t-1,u]) (1 if invalid/t<1), Lc(r,u)=exp(lab) (0 if
//   invalid/u<1), t=r-u; r<0 = identity row.
__device__ __forceinline__ float2 get_BL(const float* __restrict__ logits,
                                         const int* __restrict__ labels,
                                         int b, int r, int u) {
    if (r < 0 || u >= U1) return make_float2(1.0f, 0.0f);
    int t = r - u;
    if (t < 0 || t >= T) return make_float2(1.0f, 0.0f);
    float Bl = 1.0f, Lc = 0.0f;
    if (t >= 1)
        Bl = fexp(logits[((long)(b * T + (t - 1)) * U1 + u) * V]);
    if (u >= 1)
        Lc = fexp(logits[((long)(b * T + t) * U1 + (u - 1)) * V
                         + labels[b * (U1 - 1) + (u - 1)]]);
    return make_float2(Bl, Lc);
}

// ---------------------------------------------------------------------------
// Kernel 1: gather + compose FOUR single steps into banded quad coefficients.
// One 128-thread CTA per (batch, quad-row). ALL 128 threads run every stage
// and every __syncthreads unconditionally (R14 hung on divergent barriers);
// threads u >= U1 just carry neutral/identity entries. Only the final store
// is gated. Pad/dead rows (p >= nQuad) write zero maps. Also zero-inits out.
// ---------------------------------------------------------------------------
__global__ void __launch_bounds__(128, 8)
gather_kernel(const float* __restrict__ logits,
              const int* __restrict__ labels,
              const int* __restrict__ loglen,
              const int* __restrict__ lablen,
              float* __restrict__ out) {
    __shared__ float2 sh_s0[129];
    __shared__ float4 sh_p2[129];
    __shared__ float4 sh_p3[129];

    const int bp = blockIdx.x;                     // b * NQR + p
    const int b  = bp / NQR;
    const int p  = bp % NQR;
    const int u  = threadIdx.x;                    // 0..127
    if (bp == 0 && u == 0) out[0] = 0.0f;

    const int nSteps = loglen[b] + lablen[b];
    const int off    = (4 - (nSteps & 3)) & 3;     // identity pre-rows
    const int nQuad  = (nSteps + off) >> 2;
    const bool live  = (p < nQuad);
    const int r1     = 4 * p - off;

    // Single-step rows at this column (identity if dead row)
    float2 s0 = make_float2(1.f, 0.f), s1 = s0, s2 = s0, s3 = s0;
    if (live) {
        s0 = get_BL(logits, labels, b, r1,     u);
        s1 = get_BL(logits, labels, b, r1 + 1, u);
        s2 = get_BL(logits, labels, b, r1 + 2, u);
        s3 = get_BL(logits, labels, b, r1 + 3, u);
    }
    sh_s0[u + 1] = s0;
    if (u == 0) sh_s0[0] = make_float2(1.f, 0.f);  // identity left-neighbor
    __syncthreads();

    // Stage 2: P2 = M2*M1 (bands c0..c2) — same algebra as proven k=2
    float2 s0m = sh_s0[u];
    float c0 = s1.x * s0.x;
    float c1 = fmaf(s1.x, s0.y, s1.y * s0m.x);
    float c2 = s1.y * s0m.y;
    sh_p2[u + 1] = make_float4(c0, c1, c2, 0.f);
    if (u == 0) sh_p2[0] = make_float4(1.f, 0.f, 0.f, 0.f);
    __syncthreads();

    // Stage 3: P3 = M3*P2 (bands d0..d3)
    float4 p2m = sh_p2[u];
    float d0 = s2.x * c0;
    float d1 = fmaf(s2.x, c1, s2.y * p2m.x);
    float d2 = fmaf(s2.x, c2, s2.y * p2m.y);
    float d3 = s2.y * p2m.z;
    sh_p3[u + 1] = make_float4(d0, d1, d2, d3);
    if (u == 0) sh_p3[0] = make_float4(1.f, 0.f, 0.f, 0.f);
    __syncthreads();

    // Stage 4: P4 = M4*P3 (bands e0..e4)
    float4 p3m = sh_p3[u];
    float e0 = 0.f, e1 = 0.f, e2 = 0.f, e3 = 0.f, e4 = 0.f;
    if (live) {
        e0 = s3.x * d0;
        e1 = fmaf(s3.x, d1, s3.y * p3m.x);
        e2 = fmaf(s3.x, d2, s3.y * p3m.y);
        e3 = fmaf(s3.x, d3, s3.y * p3m.z);
        e4 = s3.y * p3m.w;
    }
    if (u >= UD) return;

    int idx = (b * NQR + p) * UD + u;
    __nv_bfloat162 a01 = __floats2bfloat162_rn(e0, e1);
    __nv_bfloat162 b23 = __floats2bfloat162_rn(e2, e3);
    g_qA[idx] = *reinterpret_cast<uint32_t*>(&a01);
    g_qB[idx] = *reinterpret_cast<uint32_t*>(&b23);
    g_qC[idx] = __float2bfloat16_rn(e4);
}

// ---------------------------------------------------------------------------
// Kernel 2: one 32-thread CTA per batch. Chunked bulk-copy staging
// (8/24/24/24 quad rows -> tiny first wait). Quad-step wavefront: every step
// reads only OLD state; 4 shfls + 20 FMA per step covering 4 diagonals.
// Exact power-of-2 renorm every 4 quad-steps (= 16 diagonals, proven
// cadence). Final block snapshots at quad capRem.
// ---------------------------------------------------------------------------
struct DPState { float a0, a1, a2, a3; };
struct QuadBuf { uint4 ab01[4]; uint4 ab23[4]; uint2 c4[4]; };

__device__ __forceinline__ float bflo(uint32_t x) {
    return __int_as_float((int)(x << 16));
}
__device__ __forceinline__ float bfhi(uint32_t x) {
    return __int_as_float((int)(x & 0xFFFF0000u));
}

__device__ __forceinline__ void quad_step(DPState& s, uint4 ab01, uint4 ab23,
                                          uint2 c4, int lsrc) {
    float p3 = __shfl_sync(0xffffffffu, s.a3, lsrc);
    float p2 = __shfl_sync(0xffffffffu, s.a2, lsrc);
    float p1 = __shfl_sync(0xffffffffu, s.a1, lsrc);
    float p0 = __shfl_sync(0xffffffffu, s.a0, lsrc);
    float n0 = fmaf(bflo(ab01.x), s.a0,
               fmaf(bfhi(ab01.x), p3,
               fmaf(bflo(ab23.x), p2,
               fmaf(bfhi(ab23.x), p1, bflo(c4.x) * p0))));
    float n1 = fmaf(bflo(ab01.y), s.a1,
               fmaf(bfhi(ab01.y), s.a0,
               fmaf(bflo(ab23.y), p3,
               fmaf(bfhi(ab23.y), p2, bfhi(c4.x) * p1))));
    float n2 = fmaf(bflo(ab01.z), s.a2,
               fmaf(bfhi(ab01.z), s.a1,
               fmaf(bflo(ab23.z), s.a0,
               fmaf(bfhi(ab23.z), p3, bflo(c4.y) * p2))));
    float n3 = fmaf(bflo(ab01.w), s.a3,
               fmaf(bfhi(ab01.w), s.a2,
               fmaf(bflo(ab23.w), s.a1,
               fmaf(bfhi(ab23.w), s.a0, bfhi(c4.y) * p3))));
    s.a0 = n0; s.a1 = n1; s.a2 = n2; s.a3 = n3;
}

__device__ __forceinline__ void renorm(DPState& s, int& S) {
    float mx = fmaxf(fmaxf(s.a0, s.a1), fmaxf(s.a2, s.a3));
    unsigned mxi = __reduce_max_sync(0xffffffffu, (unsigned)__float_as_int(mx));
    int e = (int)(mxi >> 23) - 127;
    float sc = __int_as_float((127 - e) << 23);    // 2^-e, exact
    s.a0 *= sc; s.a1 *= sc; s.a2 *= sc; s.a3 *= sc;
    S += e;
}

__constant__ int c_chunk_start[5] = {0, 8, 32, 56, 80};

__global__ void __launch_bounds__(32, 1)
dp_kernel(const int* __restrict__ loglen,
          const int* __restrict__ lablen,
          float* __restrict__ out) {
    extern __shared__ __align__(16) char sm[];
    uint32_t* smA = reinterpret_cast<uint32_t*>(sm);                  // 33280 B
    uint32_t* smB = reinterpret_cast<uint32_t*>(sm + NQR * UD * 4);   // 33280 B
    __nv_bfloat16* smC =
        reinterpret_cast<__nv_bfloat16*>(sm + 2 * NQR * UD * 4);      // 16640 B
    __shared__ __align__(8) unsigned long long mbars[4];

    const int b    = blockIdx.x;
    const int lane = threadIdx.x;
    const int lsrc = (lane + 31) & 31;

    if (lane == 0) {
        #pragma unroll
        for (int c = 0; c < 4; ++c)
            asm volatile("mbarrier.init.shared.b64 [%0], %1;"
                         :: "r"(smem_u32(&mbars[c])), "r"(1) : "memory");
        asm volatile("fence.proxy.async.shared::cta;" ::: "memory");
        #pragma unroll 1
        for (int c = 0; c < 4; ++c) {
            int rs = c_chunk_start[c], rn = c_chunk_start[c + 1] - rs;
            uint32_t txA = rn * UD * 4u, txC = rn * UD * 2u;
            uint32_t mb = smem_u32(&mbars[c]);
            asm volatile("mbarrier.arrive.expect_tx.shared.b64 _, [%0], %1;"
                         :: "r"(mb), "r"(2 * txA + txC) : "memory");
            asm volatile(
                "cp.async.bulk.shared::cluster.global.mbarrier::complete_tx::bytes"
                " [%0], [%1], %2, [%3];"
                :: "r"(smem_u32(smA + rs * UD)),
                   "l"(g_qA + (size_t)(b * NQR + rs) * UD),
                   "r"(txA), "r"(mb) : "memory");
            asm volatile(
                "cp.async.bulk.shared::cluster.global.mbarrier::complete_tx::bytes"
                " [%0], [%1], %2, [%3];"
                :: "r"(smem_u32(smB + rs * UD)),
                   "l"(g_qB + (size_t)(b * NQR + rs) * UD),
                   "r"(txA), "r"(mb) : "memory");
            asm volatile(
                "cp.async.bulk.shared::cluster.global.mbarrier::complete_tx::bytes"
                " [%0], [%1], %2, [%3];"
                :: "r"(smem_u32(smC + rs * UD)),
                   "l"(g_qC + (size_t)(b * NQR + rs) * UD),
                   "r"(txC), "r"(mb) : "memory");
        }
    }
    __syncwarp();

    int cw = 0;
    auto ensure = [&](int c) {
        while (cw <= c) {
            uint32_t mb = smem_u32(&mbars[cw]);
            uint32_t done = 0;
            while (!done)
                asm volatile(
                    "{\n\t.reg .pred p;\n\t"
                    "mbarrier.try_wait.parity.acquire.cta.shared::cta.b64 p, [%1], %2;\n\t"
                    "selp.b32 %0, 1, 0, p;\n\t}"
                    : "=r"(done) : "r"(mb), "r"(0u) : "memory");
            ++cw;
        }
    };
    auto cb = [](int blk) {                        // chunk holding row 4*blk+3
        int rl = 4 * blk + 3;
        return (rl < 8) ? 0 : (rl < 32) ? 1 : (rl < 56) ? 2 : 3;
    };

    const int Tb     = loglen[b];
    const int Lb     = lablen[b];
    const int nSteps = Tb + Lb;
    const int offq   = (4 - (nSteps & 3)) & 3;
    const int nQuad  = (nSteps + offq) >> 2;       // <= 75
    const int blkTot = (nQuad + 3) >> 2;           // 4 quads per block
    const int nFull  = blkTot - 1;
    const int capRem = (nQuad - 1) - nFull * 4;    // 0..3 snapshot step

    DPState s;
    s.a0 = (lane == 0) ? 1.0f : 0.0f;
    s.a1 = 0.0f; s.a2 = 0.0f; s.a3 = 0.0f;
    int S = 0;
    float c0 = 0.0f, c1 = 0.0f, c2 = 0.0f, c3 = 0.0f;

    const uint4* pa = reinterpret_cast<const uint4*>(smA) + lane;
    const uint4* pb = reinterpret_cast<const uint4*>(smB) + lane;
    const uint2* pc = reinterpret_cast<const uint2*>(smC) + lane;

    QuadBuf bufA, bufB;
    auto pref = [&](QuadBuf& buf, int blk) {
        int base = blk * 4 * 26;
        #pragma unroll
        for (int k = 0; k < 4; ++k) {
            buf.ab01[k] = pa[base + k * 26];
            buf.ab23[k] = pb[base + k * 26];
            buf.c4[k]   = pc[base + k * 26];
        }
    };
    auto comp = [&](QuadBuf& buf) {
        renorm(s, S);                              // every 16 diagonals
        #pragma unroll
        for (int k = 0; k < 4; ++k)
            quad_step(s, buf.ab01[k], buf.ab23[k], buf.c4[k], lsrc);
    };
    auto compLast = [&](QuadBuf& buf) {
        renorm(s, S);
        #pragma unroll
        for (int k = 0; k < 4; ++k) {
            quad_step(s, buf.ab01[k], buf.ab23[k], buf.c4[k], lsrc);
            if (k == capRem) { c0 = s.a0; c1 = s.a1; c2 = s.a2; c3 = s.a3; }
        }
    };

    ensure(cb(0));
    pref(bufA, 0);
    int blk = 0;
    #pragma unroll 1
    while (blk + 2 <= nFull) {
        ensure(cb(blk + 1)); pref(bufB, blk + 1); comp(bufA);
        ensure(cb(blk + 2)); pref(bufA, blk + 2); comp(bufB);
        blk += 2;
    }
    if (blk == nFull) {
        compLast(bufA);
    } else {
        ensure(cb(blk + 1)); pref(bufB, blk + 1); comp(bufA);
        compLast(bufB);
    }

    if (lane == (Lb >> 2)) {
        int ck = Lb & 3;
        float cap = (ck == 0) ? c0 : (ck == 1) ? c1 : (ck == 2) ? c2 : c3;
        float loss = -(log2f(cap) + (float)S) * LN2;   // back to nats
        atomicAdd(out, loss * (1.0f / B));             // mean over batch
    }
}

// ---------------------------------------------------------------------------
extern "C" void kernel_launch(void* const* d_in, const int* in_sizes, int n_in,
                              void* d_out, int out_size) {
    const float* logits = (const float*)d_in[0];
    const int*   labels = (const int*)d_in[1];
    const int*   loglen = (const int*)d_in[2];
    const int*   lablen = (const int*)d_in[3];
    float* out = (float*)d_out;

    const int smem_bytes = 2 * NQR * UD * 4 + NQR * UD * 2;  // 83200 B

    cudaFuncSetAttribute(dp_kernel,
                         cudaFuncAttributeMaxDynamicSharedMemorySize,
                         smem_bytes);

    gather_kernel<<<B * NQR, 128>>>(logits, labels, loglen, lablen, out);
    dp_kernel<<<B, 32, smem_bytes>>>(loglen, lablen, out);
}